// round 1
// baseline (speedup 1.0000x reference)
#include <cuda_runtime.h>
#include <math.h>

// Problem constants
#define BB   8
#define NN   4096
#define CC   768
#define HH   8
#define HD   96
#define MROWS (BB*NN)      // 32768
#define K3C   (3*CC)       // 2304
#define BHD   (BB*HH*HD)   // 6144

// ---------------- scratch (device globals; no allocs allowed) ----------------
__device__ float g_q[BB*HH*HD*NN];        // [b][h][d][n]
__device__ float g_k[BB*HH*HD*NN];
__device__ float g_v[BB*HH*HD*NN];
__device__ float g_nq[BHD];               // per-row L2 norms (clamped)
__device__ float g_nk[BHD];
__device__ float g_gram[BB*HH*HD*HD];     // Gram / attention matrices
__device__ float g_ao[MROWS*CC];          // attention output, (B,N,C) row-major

// ---------------- kernel 0: zero gram accumulator ----------------
__global__ void zero_gram_kernel() {
    int i = blockIdx.x * blockDim.x + threadIdx.x;
    if (i < BB*HH*HD*HD) g_gram[i] = 0.0f;
}

// ---------------- kernel 1: QKV GEMM, C = x @ w_qkv^T, scatter to q/k/v ----
// M=32768, K=768, Ncol=2304. 128x128 tile, kt=16, 256 threads, 8x8 per thread.
__global__ __launch_bounds__(256) void gemm_qkv_kernel(
    const float* __restrict__ A, const float* __restrict__ W)
{
    __shared__ __align__(16) float As[16][128];
    __shared__ __align__(16) float Bs[16][128];
    const int tid = threadIdx.x;
    const int tx = tid & 15, ty = tid >> 4;
    const int m0 = blockIdx.y * 128;
    const int n0 = blockIdx.x * 128;

    float acc[8][8];
#pragma unroll
    for (int i = 0; i < 8; i++)
#pragma unroll
        for (int j = 0; j < 8; j++) acc[i][j] = 0.0f;

    for (int k0 = 0; k0 < CC; k0 += 16) {
#pragma unroll
        for (int r = 0; r < 2; r++) {
            int idx = r * 256 + tid;       // 0..511
            int mm = idx >> 2;
            int kk4 = (idx & 3) * 4;
            float4 va = *(const float4*)(A + (size_t)(m0 + mm) * CC + k0 + kk4);
            As[kk4 + 0][mm] = va.x; As[kk4 + 1][mm] = va.y;
            As[kk4 + 2][mm] = va.z; As[kk4 + 3][mm] = va.w;
            float4 vb = *(const float4*)(W + (size_t)(n0 + mm) * CC + k0 + kk4);
            Bs[kk4 + 0][mm] = vb.x; Bs[kk4 + 1][mm] = vb.y;
            Bs[kk4 + 2][mm] = vb.z; Bs[kk4 + 3][mm] = vb.w;
        }
        __syncthreads();
#pragma unroll
        for (int kk = 0; kk < 16; kk++) {
            float4 a0 = *(const float4*)&As[kk][ty * 8];
            float4 a1 = *(const float4*)&As[kk][ty * 8 + 4];
            float4 b0 = *(const float4*)&Bs[kk][tx * 8];
            float4 b1 = *(const float4*)&Bs[kk][tx * 8 + 4];
            float a[8] = {a0.x, a0.y, a0.z, a0.w, a1.x, a1.y, a1.z, a1.w};
            float b[8] = {b0.x, b0.y, b0.z, b0.w, b1.x, b1.y, b1.z, b1.w};
#pragma unroll
            for (int i = 0; i < 8; i++)
#pragma unroll
                for (int j = 0; j < 8; j++) acc[i][j] += a[i] * b[j];
        }
        __syncthreads();
    }

    // scatter epilogue into q/k/v [b][h][d][n]
#pragma unroll
    for (int i = 0; i < 8; i++) {
        int m = m0 + ty * 8 + i;
        int bb = m >> 12;
        int tok = m & (NN - 1);
#pragma unroll
        for (int j = 0; j < 8; j++) {
            int col = n0 + tx * 8 + j;
            int t = col / CC;
            int rem = col - t * CC;
            int hh = rem / HD;
            int dd = rem - hh * HD;
            float* dst = (t == 0) ? g_q : (t == 1) ? g_k : g_v;
            dst[(((size_t)(bb * HH + hh) * HD + dd) * NN) + tok] = acc[i][j];
        }
    }
}

// ---------------- kernel 2: row L2 norms over N ----------------
__global__ void norm_kernel() {
    int row = blockIdx.x;                  // 0..2*BHD-1
    bool isq = row < BHD;
    int r = isq ? row : row - BHD;
    const float* p = (isq ? g_q : g_k) + (size_t)r * NN;
    float s = 0.0f;
    for (int i = threadIdx.x; i < NN; i += 128) {
        float v = p[i];
        s += v * v;
    }
    __shared__ float red[4];
#pragma unroll
    for (int o = 16; o; o >>= 1) s += __shfl_xor_sync(0xffffffff, s, o);
    if ((threadIdx.x & 31) == 0) red[threadIdx.x >> 5] = s;
    __syncthreads();
    if (threadIdx.x == 0) {
        float t = red[0] + red[1] + red[2] + red[3];
        float nrm = fmaxf(sqrtf(t), 1e-12f);
        (isq ? g_nq : g_nk)[r] = nrm;
    }
}

// ---------------- kernel 3: Gram = q @ k^T over N (split-N, atomic) --------
// grid (16 splits, 64 heads), 256 threads, 6x6 per thread
__global__ __launch_bounds__(256) void gram_kernel() {
    const int bh = blockIdx.y;
    const int n0 = blockIdx.x * 256;
    const float* qb = g_q + (size_t)bh * HD * NN;
    const float* kb = g_k + (size_t)bh * HD * NN;
    __shared__ float qs[16][100];
    __shared__ float ks[16][100];
    const int tid = threadIdx.x;
    const int tx = tid & 15, ty = tid >> 4;

    float acc[6][6];
#pragma unroll
    for (int i = 0; i < 6; i++)
#pragma unroll
        for (int j = 0; j < 6; j++) acc[i][j] = 0.0f;

    for (int nt = 0; nt < 256; nt += 16) {
#pragma unroll
        for (int r = 0; r < 6; r++) {
            int idx = r * 256 + tid;       // 0..1535
            int nn = idx & 15;
            int d = idx >> 4;
            qs[nn][d] = qb[(size_t)d * NN + n0 + nt + nn];
            ks[nn][d] = kb[(size_t)d * NN + n0 + nt + nn];
        }
        __syncthreads();
#pragma unroll
        for (int nn = 0; nn < 16; nn++) {
            float a[6], c[6];
#pragma unroll
            for (int i = 0; i < 6; i++) a[i] = qs[nn][ty * 6 + i];
#pragma unroll
            for (int j = 0; j < 6; j++) c[j] = ks[nn][tx * 6 + j];
#pragma unroll
            for (int i = 0; i < 6; i++)
#pragma unroll
                for (int j = 0; j < 6; j++) acc[i][j] += a[i] * c[j];
        }
        __syncthreads();
    }
    float* G = g_gram + (size_t)bh * HD * HD;
#pragma unroll
    for (int i = 0; i < 6; i++)
#pragma unroll
        for (int j = 0; j < 6; j++)
            atomicAdd(&G[(ty * 6 + i) * HD + tx * 6 + j], acc[i][j]);
}

// ---------------- kernel 4: scale + softmax per (b,h) row ----------------
__global__ void softmax_kernel(const float* __restrict__ temp) {
    const int bh = blockIdx.x;
    const int h = bh & (HH - 1);
    const int d = threadIdx.x;             // 96 threads
    __shared__ float snk[HD];
    if (d < HD) snk[d] = g_nk[bh * HD + d];
    __syncthreads();
    if (d >= HD) return;
    float* row = g_gram + (size_t)bh * HD * HD + d * HD;
    const float scale = temp[h] / g_nq[bh * HD + d];
    float vals[HD];
    float mx = -1e30f;
    for (int e = 0; e < HD; e++) {
        float v = row[e] * scale / snk[e];
        vals[e] = v;
        mx = fmaxf(mx, v);
    }
    float s = 0.0f;
    for (int e = 0; e < HD; e++) {
        float ex = expf(vals[e] - mx);
        vals[e] = ex;
        s += ex;
    }
    float inv = 1.0f / s;
    for (int e = 0; e < HD; e++) row[e] = vals[e] * inv;
}

// ---------------- kernel 5: out = A @ v, write (B,N,C) layout ----------------
// grid (32 token tiles, 64 heads), 256 threads, 6(d)x8(n) per thread
__global__ __launch_bounds__(256) void av_kernel() {
    const int bh = blockIdx.y;
    const int n0 = blockIdx.x * 128;
    const int bb = bh >> 3, h = bh & 7;
    __shared__ float Asm[HD][97];
    __shared__ float vs[16][128];
    const int tid = threadIdx.x;
    const int tx = tid & 15, ty = tid >> 4;

    const float* G = g_gram + (size_t)bh * HD * HD;
#pragma unroll
    for (int r = 0; r < 36; r++) {
        int idx = r * 256 + tid;           // 0..9215
        Asm[idx / HD][idx % HD] = G[idx];
    }
    const float* vb = g_v + (size_t)bh * HD * NN;

    float acc[6][8];
#pragma unroll
    for (int i = 0; i < 6; i++)
#pragma unroll
        for (int j = 0; j < 8; j++) acc[i][j] = 0.0f;

    for (int e0 = 0; e0 < HD; e0 += 16) {
#pragma unroll
        for (int r = 0; r < 8; r++) {
            int idx = r * 256 + tid;       // 0..2047
            int nn = idx & 127;
            int ee = idx >> 7;
            vs[ee][nn] = vb[(size_t)(e0 + ee) * NN + n0 + nn];
        }
        __syncthreads();
#pragma unroll
        for (int ee = 0; ee < 16; ee++) {
            float a[6], vv[8];
#pragma unroll
            for (int i = 0; i < 6; i++) a[i] = Asm[ty * 6 + i][e0 + ee];
#pragma unroll
            for (int j = 0; j < 8; j++) vv[j] = vs[ee][tx + j * 16];
#pragma unroll
            for (int i = 0; i < 6; i++)
#pragma unroll
                for (int j = 0; j < 8; j++) acc[i][j] += a[i] * vv[j];
        }
        __syncthreads();
    }
#pragma unroll
    for (int i = 0; i < 6; i++) {
        int d = ty * 6 + i;
#pragma unroll
        for (int j = 0; j < 8; j++) {
            int n = n0 + tx + j * 16;
            g_ao[((size_t)(bb * NN + n)) * CC + h * HD + d] = acc[i][j];
        }
    }
}

// ---------------- kernel 6: proj GEMM, out = g_ao @ w_proj^T + b ------------
__global__ __launch_bounds__(256) void gemm_proj_kernel(
    const float* __restrict__ W, const float* __restrict__ bias,
    float* __restrict__ out)
{
    __shared__ __align__(16) float As[16][128];
    __shared__ __align__(16) float Bs[16][128];
    const int tid = threadIdx.x;
    const int tx = tid & 15, ty = tid >> 4;
    const int m0 = blockIdx.y * 128;
    const int n0 = blockIdx.x * 128;

    float acc[8][8];
#pragma unroll
    for (int i = 0; i < 8; i++)
#pragma unroll
        for (int j = 0; j < 8; j++) acc[i][j] = 0.0f;

    for (int k0 = 0; k0 < CC; k0 += 16) {
#pragma unroll
        for (int r = 0; r < 2; r++) {
            int idx = r * 256 + tid;
            int mm = idx >> 2;
            int kk4 = (idx & 3) * 4;
            float4 va = *(const float4*)(g_ao + (size_t)(m0 + mm) * CC + k0 + kk4);
            As[kk4 + 0][mm] = va.x; As[kk4 + 1][mm] = va.y;
            As[kk4 + 2][mm] = va.z; As[kk4 + 3][mm] = va.w;
            float4 vb = *(const float4*)(W + (size_t)(n0 + mm) * CC + k0 + kk4);
            Bs[kk4 + 0][mm] = vb.x; Bs[kk4 + 1][mm] = vb.y;
            Bs[kk4 + 2][mm] = vb.z; Bs[kk4 + 3][mm] = vb.w;
        }
        __syncthreads();
#pragma unroll
        for (int kk = 0; kk < 16; kk++) {
            float4 a0 = *(const float4*)&As[kk][ty * 8];
            float4 a1 = *(const float4*)&As[kk][ty * 8 + 4];
            float4 b0 = *(const float4*)&Bs[kk][tx * 8];
            float4 b1 = *(const float4*)&Bs[kk][tx * 8 + 4];
            float a[8] = {a0.x, a0.y, a0.z, a0.w, a1.x, a1.y, a1.z, a1.w};
            float b[8] = {b0.x, b0.y, b0.z, b0.w, b1.x, b1.y, b1.z, b1.w};
#pragma unroll
            for (int i = 0; i < 8; i++)
#pragma unroll
                for (int j = 0; j < 8; j++) acc[i][j] += a[i] * b[j];
        }
        __syncthreads();
    }
#pragma unroll
    for (int i = 0; i < 8; i++) {
        int m = m0 + ty * 8 + i;
#pragma unroll
        for (int j = 0; j < 8; j++) {
            int col = n0 + tx * 8 + j;
            out[(size_t)m * CC + col] = acc[i][j] + bias[col];
        }
    }
}

// ---------------- launch ----------------
extern "C" void kernel_launch(void* const* d_in, const int* in_sizes, int n_in,
                              void* d_out, int out_size)
{
    const float* x      = (const float*)d_in[0];
    const float* w_qkv  = (const float*)d_in[1];
    const float* temp   = (const float*)d_in[2];
    const float* w_proj = (const float*)d_in[3];
    const float* b_proj = (const float*)d_in[4];
    float* out = (float*)d_out;

    zero_gram_kernel<<<576, 1024>>>();
    gemm_qkv_kernel<<<dim3(K3C / 128, MROWS / 128), 256>>>(x, w_qkv);
    norm_kernel<<<2 * BHD, 128>>>();
    gram_kernel<<<dim3(16, BB * HH), 256>>>();
    softmax_kernel<<<BB * HH, 96>>>(temp);
    av_kernel<<<dim3(NN / 128, BB * HH), 256>>>();
    gemm_proj_kernel<<<dim3(CC / 128, MROWS / 128), 256>>>(w_proj, b_proj, out);
}

// round 3
// speedup vs baseline: 2.4189x; 2.4189x over previous
#include <cuda_runtime.h>
#include <cuda_bf16.h>
#include <math.h>
#include <stdint.h>

// Problem constants
#define BB   8
#define NN   4096
#define CC   768
#define HH   8
#define HD   96
#define MROWS (BB*NN)      // 32768
#define K3C   (3*CC)       // 2304
#define BHD   (BB*HH*HD)   // 6144

// ---------------- scratch (device globals; no allocs allowed) ----------------
__device__ __align__(256) float g_q[BB*HH*HD*NN];        // [b][h][d][n]
__device__ __align__(256) float g_k[BB*HH*HD*NN];
__device__ __align__(256) float g_v[BB*HH*HD*NN];
__device__ __align__(256) float g_nq[BHD];
__device__ __align__(256) float g_nk[BHD];
__device__ __align__(256) float g_gram[BB*HH*HD*HD];
__device__ __align__(256) float g_ao[MROWS*CC];          // (B,N,C) row-major

// ======================= mma.sync helpers =======================
__device__ __forceinline__ uint32_t smem_u32(const void* p) {
    uint32_t a;
    asm("{ .reg .u64 t; cvta.to.shared.u64 t, %1; cvt.u32.u64 %0, t; }"
        : "=r"(a) : "l"(p));
    return a;
}
__device__ __forceinline__ void ldm_x4(uint32_t* r, uint32_t addr) {
    asm volatile("ldmatrix.sync.aligned.m8n8.x4.shared.b16 {%0,%1,%2,%3}, [%4];"
        : "=r"(r[0]), "=r"(r[1]), "=r"(r[2]), "=r"(r[3]) : "r"(addr));
}
__device__ __forceinline__ void mma_bf16(float* c, const uint32_t* a, const uint32_t* b) {
    asm volatile("mma.sync.aligned.m16n8k16.row.col.f32.bf16.bf16.f32 "
        "{%0,%1,%2,%3}, {%4,%5,%6,%7}, {%8,%9}, {%0,%1,%2,%3};"
        : "+f"(c[0]), "+f"(c[1]), "+f"(c[2]), "+f"(c[3])
        : "r"(a[0]), "r"(a[1]), "r"(a[2]), "r"(a[3]), "r"(b[0]), "r"(b[1]));
}

// smem tile geometry: 128 rows x 32 bf16, padded stride 40 bf16 (80B, 16B-aligned,
// conflict-free for ldmatrix: r*20 mod 32 distinct over 8 rows)
#define TROW 80                     // bytes per row
#define TSZ  (128*TROW)             // 10240 B per tile
#define STAGE (4*TSZ)               // Ahi, Alo, Bhi, Blo
#define DSMEM (2*STAGE)             // 81920 B
#define KC 32
#define NCH (CC/KC)                 // 24

// split fp32 float4 -> hi/lo bf16x4, store 8B each
__device__ __forceinline__ void split_store(char* hi, char* lo, float4 v) {
    __nv_bfloat162 h0 = __float22bfloat162_rn(make_float2(v.x, v.y));
    __nv_bfloat162 h1 = __float22bfloat162_rn(make_float2(v.z, v.w));
    float2 r0 = make_float2(v.x - __bfloat162float(h0.x), v.y - __bfloat162float(h0.y));
    float2 r1 = make_float2(v.z - __bfloat162float(h1.x), v.w - __bfloat162float(h1.y));
    __nv_bfloat162 l0 = __float22bfloat162_rn(r0);
    __nv_bfloat162 l1 = __float22bfloat162_rn(r1);
    uint2 uh, ul;
    uh.x = *reinterpret_cast<uint32_t*>(&h0); uh.y = *reinterpret_cast<uint32_t*>(&h1);
    ul.x = *reinterpret_cast<uint32_t*>(&l0); ul.y = *reinterpret_cast<uint32_t*>(&l1);
    *(uint2*)hi = uh;
    *(uint2*)lo = ul;
}

// mainloop: acc[i(m16)][j(n8)][reg], A rows->M, B rows->N, both K-major ld=CC
__device__ __forceinline__ void mma_mainloop(
    const float* __restrict__ A, const float* __restrict__ B,
    int m0, int n0, float acc[4][4][4], char* sm)
{
    const int tid = threadIdx.x;
    const int wid = tid >> 5, lane = tid & 31;
    const int wm = (wid >> 2) * 64;
    const int wn = (wid & 3) * 32;
    const uint32_t sbase = smem_u32(sm);

    const int lrow = tid >> 3;          // 0..31
    const int lc4 = (tid & 7) * 4;      // col (floats)

    // per-lane ldmatrix address bases (byte offsets within a tile)
    const uint32_t a_l = (uint32_t)(wm + (lane & 15)) * TROW + ((lane >> 4) << 4);
    const uint32_t b_l = (uint32_t)(wn + (lane & 7) + ((lane >> 4) & 1) * 8) * TROW
                       + (((lane >> 3) & 1) << 4);

    float4 ra[4], rb[4];
#pragma unroll
    for (int it = 0; it < 4; it++) {
        ra[it] = *(const float4*)(A + (size_t)(m0 + lrow + it * 32) * CC + lc4);
        rb[it] = *(const float4*)(B + (size_t)(n0 + lrow + it * 32) * CC + lc4);
    }
#pragma unroll
    for (int it = 0; it < 4; it++) {
        int off = (lrow + it * 32) * TROW + lc4 * 2;
        split_store(sm + off, sm + TSZ + off, ra[it]);
        split_store(sm + 2 * TSZ + off, sm + 3 * TSZ + off, rb[it]);
    }
    __syncthreads();

    for (int c = 0; c < NCH; c++) {
        if (c < NCH - 1) {
            int k0 = (c + 1) * KC;
#pragma unroll
            for (int it = 0; it < 4; it++) {
                ra[it] = *(const float4*)(A + (size_t)(m0 + lrow + it * 32) * CC + k0 + lc4);
                rb[it] = *(const float4*)(B + (size_t)(n0 + lrow + it * 32) * CC + k0 + lc4);
            }
        }
        // compute current stage
        const uint32_t st = sbase + (uint32_t)(c & 1) * STAGE;
#pragma unroll
        for (int kk = 0; kk < 2; kk++) {
            uint32_t ah[4][4], al[4][4], bh[2][4], bl[2][4];
#pragma unroll
            for (int i = 0; i < 4; i++) {
                uint32_t ad = st + a_l + kk * 32 + i * 16 * TROW;
                ldm_x4(ah[i], ad);
                ldm_x4(al[i], ad + TSZ);
            }
#pragma unroll
            for (int j = 0; j < 2; j++) {
                uint32_t bd = st + 2 * TSZ + b_l + kk * 32 + j * 16 * TROW;
                ldm_x4(bh[j], bd);
                ldm_x4(bl[j], bd + TSZ);
            }
#pragma unroll
            for (int i = 0; i < 4; i++)
#pragma unroll
                for (int j4 = 0; j4 < 4; j4++) {
                    const uint32_t* bhp = &bh[j4 >> 1][(j4 & 1) * 2];
                    const uint32_t* blp = &bl[j4 >> 1][(j4 & 1) * 2];
                    mma_bf16(acc[i][j4], ah[i], bhp);
                    mma_bf16(acc[i][j4], ah[i], blp);
                    mma_bf16(acc[i][j4], al[i], bhp);
                }
        }
        if (c < NCH - 1) {
            char* ns = sm + ((c + 1) & 1) * STAGE;
#pragma unroll
            for (int it = 0; it < 4; it++) {
                int off = (lrow + it * 32) * TROW + lc4 * 2;
                split_store(ns + off, ns + TSZ + off, ra[it]);
                split_store(ns + 2 * TSZ + off, ns + 3 * TSZ + off, rb[it]);
            }
        }
        __syncthreads();
    }
}

// ---- QKV GEMM: M = qkv features (w rows), N = tokens; scatter to q/k/v [d][n]
__global__ __launch_bounds__(256, 1) void gemm_qkv_mma(
    const float* __restrict__ x, const float* __restrict__ w)
{
    extern __shared__ char sm[];
    const int m0 = blockIdx.x * 128;   // feature tile (of 2304)
    const int n0 = blockIdx.y * 128;   // token tile (of 32768)
    float acc[4][4][4];
#pragma unroll
    for (int i = 0; i < 4; i++)
#pragma unroll
        for (int j = 0; j < 4; j++)
#pragma unroll
            for (int r = 0; r < 4; r++) acc[i][j][r] = 0.0f;

    mma_mainloop(w, x, m0, n0, acc, sm);

    const int tid = threadIdx.x;
    const int wid = tid >> 5, lane = tid & 31;
    const int wm = (wid >> 2) * 64, wn = (wid & 3) * 32;
    const int b = n0 >> 12;            // token tile within one batch
    const int ntk = (n0 & (NN - 1)) + wn + (lane & 3) * 2;
#pragma unroll
    for (int i = 0; i < 4; i++) {
#pragma unroll
        for (int half = 0; half < 2; half++) {
            int f = m0 + wm + i * 16 + (lane >> 2) + half * 8;
            int t = f / CC;
            int rem = f - t * CC;
            int h = rem / HD, d = rem - h * HD;
            float* dst = (t == 0) ? g_q : (t == 1) ? g_k : g_v;
            float* rowp = dst + ((size_t)(b * HH + h) * HD + d) * NN;
#pragma unroll
            for (int j4 = 0; j4 < 4; j4++) {
                *(float2*)&rowp[ntk + j4 * 8] =
                    make_float2(acc[i][j4][half * 2], acc[i][j4][half * 2 + 1]);
            }
        }
    }
}

// ---- Proj GEMM: M = tokens (g_ao rows), N = out features; out coalesced ----
__global__ __launch_bounds__(256, 1) void gemm_proj_mma(
    const float* __restrict__ w, const float* __restrict__ bias,
    float* __restrict__ out)
{
    extern __shared__ char sm[];
    const int n0 = blockIdx.x * 128;   // feature tile (of 768)
    const int m0 = blockIdx.y * 128;   // token tile
    float acc[4][4][4];
#pragma unroll
    for (int i = 0; i < 4; i++)
#pragma unroll
        for (int j = 0; j < 4; j++)
#pragma unroll
            for (int r = 0; r < 4; r++) acc[i][j][r] = 0.0f;

    mma_mainloop(g_ao, w, m0, n0, acc, sm);

    const int tid = threadIdx.x;
    const int wid = tid >> 5, lane = tid & 31;
    const int wm = (wid >> 2) * 64, wn = (wid & 3) * 32;
    float2 bv[4];
#pragma unroll
    for (int j4 = 0; j4 < 4; j4++)
        bv[j4] = *(const float2*)&bias[n0 + wn + j4 * 8 + (lane & 3) * 2];
#pragma unroll
    for (int i = 0; i < 4; i++) {
#pragma unroll
        for (int half = 0; half < 2; half++) {
            int tok = m0 + wm + i * 16 + (lane >> 2) + half * 8;
            float* rowp = out + (size_t)tok * CC + n0 + wn + (lane & 3) * 2;
#pragma unroll
            for (int j4 = 0; j4 < 4; j4++) {
                *(float2*)&rowp[j4 * 8] =
                    make_float2(acc[i][j4][half * 2] + bv[j4].x,
                                acc[i][j4][half * 2 + 1] + bv[j4].y);
            }
        }
    }
}

// ---------------- kernel 0: zero gram accumulator ----------------
__global__ void zero_gram_kernel() {
    int i = blockIdx.x * blockDim.x + threadIdx.x;
    if (i < BB*HH*HD*HD) g_gram[i] = 0.0f;
}

// ---------------- kernel 2: row L2 norms over N ----------------
__global__ void norm_kernel() {
    int row = blockIdx.x;
    bool isq = row < BHD;
    int r = isq ? row : row - BHD;
    const float* p = (isq ? g_q : g_k) + (size_t)r * NN;
    float s = 0.0f;
    for (int i = threadIdx.x; i < NN; i += 128) {
        float v = p[i];
        s += v * v;
    }
    __shared__ float red[4];
#pragma unroll
    for (int o = 16; o; o >>= 1) s += __shfl_xor_sync(0xffffffff, s, o);
    if ((threadIdx.x & 31) == 0) red[threadIdx.x >> 5] = s;
    __syncthreads();
    if (threadIdx.x == 0) {
        float t = red[0] + red[1] + red[2] + red[3];
        (isq ? g_nq : g_nk)[r] = fmaxf(sqrtf(t), 1e-12f);
    }
}

// ---------------- kernel 3: Gram = q @ k^T over N (split-N, atomic) --------
__global__ __launch_bounds__(256) void gram_kernel() {
    const int bh = blockIdx.y;
    const int n0 = blockIdx.x * 256;
    const float* qb = g_q + (size_t)bh * HD * NN;
    const float* kb = g_k + (size_t)bh * HD * NN;
    __shared__ float qs[16][100];
    __shared__ float ks[16][100];
    const int tid = threadIdx.x;
    const int tx = tid & 15, ty = tid >> 4;

    float acc[6][6];
#pragma unroll
    for (int i = 0; i < 6; i++)
#pragma unroll
        for (int j = 0; j < 6; j++) acc[i][j] = 0.0f;

    for (int nt = 0; nt < 256; nt += 16) {
#pragma unroll
        for (int r = 0; r < 6; r++) {
            int idx = r * 256 + tid;
            int nn = idx & 15;
            int d = idx >> 4;
            qs[nn][d] = qb[(size_t)d * NN + n0 + nt + nn];
            ks[nn][d] = kb[(size_t)d * NN + n0 + nt + nn];
        }
        __syncthreads();
#pragma unroll
        for (int nn = 0; nn < 16; nn++) {
            float a[6], c[6];
#pragma unroll
            for (int i = 0; i < 6; i++) a[i] = qs[nn][ty * 6 + i];
#pragma unroll
            for (int j = 0; j < 6; j++) c[j] = ks[nn][tx * 6 + j];
#pragma unroll
            for (int i = 0; i < 6; i++)
#pragma unroll
                for (int j = 0; j < 6; j++) acc[i][j] += a[i] * c[j];
        }
        __syncthreads();
    }
    float* G = g_gram + (size_t)bh * HD * HD;
#pragma unroll
    for (int i = 0; i < 6; i++)
#pragma unroll
        for (int j = 0; j < 6; j++)
            atomicAdd(&G[(ty * 6 + i) * HD + tx * 6 + j], acc[i][j]);
}

// ---------------- kernel 4: scale + softmax per (b,h) row ----------------
__global__ void softmax_kernel(const float* __restrict__ temp) {
    const int bh = blockIdx.x;
    const int h = bh & (HH - 1);
    const int d = threadIdx.x;
    __shared__ float snk[HD];
    if (d < HD) snk[d] = g_nk[bh * HD + d];
    __syncthreads();
    if (d >= HD) return;
    float* row = g_gram + (size_t)bh * HD * HD + d * HD;
    const float scale = temp[h] / g_nq[bh * HD + d];
    float vals[HD];
    float mx = -1e30f;
    for (int e = 0; e < HD; e++) {
        float v = row[e] * scale / snk[e];
        vals[e] = v;
        mx = fmaxf(mx, v);
    }
    float s = 0.0f;
    for (int e = 0; e < HD; e++) {
        float ex = expf(vals[e] - mx);
        vals[e] = ex;
        s += ex;
    }
    float inv = 1.0f / s;
    for (int e = 0; e < HD; e++) row[e] = vals[e] * inv;
}

// ---------------- kernel 5: out = A @ v, write (B,N,C) layout ----------------
__global__ __launch_bounds__(256) void av_kernel() {
    const int bh = blockIdx.y;
    const int n0 = blockIdx.x * 128;
    const int bb = bh >> 3, h = bh & 7;
    __shared__ float Asm[HD][97];
    __shared__ float vs[16][128];
    const int tid = threadIdx.x;
    const int tx = tid & 15, ty = tid >> 4;

    const float* G = g_gram + (size_t)bh * HD * HD;
#pragma unroll
    for (int r = 0; r < 36; r++) {
        int idx = r * 256 + tid;
        Asm[idx / HD][idx % HD] = G[idx];
    }
    const float* vb = g_v + (size_t)bh * HD * NN;

    float acc[6][8];
#pragma unroll
    for (int i = 0; i < 6; i++)
#pragma unroll
        for (int j = 0; j < 8; j++) acc[i][j] = 0.0f;

    for (int e0 = 0; e0 < HD; e0 += 16) {
#pragma unroll
        for (int r = 0; r < 8; r++) {
            int idx = r * 256 + tid;
            int nn = idx & 127;
            int ee = idx >> 7;
            vs[ee][nn] = vb[(size_t)(e0 + ee) * NN + n0 + nn];
        }
        __syncthreads();
#pragma unroll
        for (int ee = 0; ee < 16; ee++) {
            float a[6], vv[8];
#pragma unroll
            for (int i = 0; i < 6; i++) a[i] = Asm[ty * 6 + i][e0 + ee];
#pragma unroll
            for (int j = 0; j < 8; j++) vv[j] = vs[ee][tx + j * 16];
#pragma unroll
            for (int i = 0; i < 6; i++)
#pragma unroll
                for (int j = 0; j < 8; j++) acc[i][j] += a[i] * vv[j];
        }
        __syncthreads();
    }
#pragma unroll
    for (int i = 0; i < 6; i++) {
        int d = ty * 6 + i;
#pragma unroll
        for (int j = 0; j < 8; j++) {
            int n = n0 + tx + j * 16;
            g_ao[((size_t)(bb * NN + n)) * CC + h * HD + d] = acc[i][j];
        }
    }
}

// ---------------- launch ----------------
extern "C" void kernel_launch(void* const* d_in, const int* in_sizes, int n_in,
                              void* d_out, int out_size)
{
    const float* x      = (const float*)d_in[0];
    const float* w_qkv  = (const float*)d_in[1];
    const float* temp   = (const float*)d_in[2];
    const float* w_proj = (const float*)d_in[3];
    const float* b_proj = (const float*)d_in[4];
    float* out = (float*)d_out;

    cudaFuncSetAttribute(gemm_qkv_mma, cudaFuncAttributeMaxDynamicSharedMemorySize, DSMEM);
    cudaFuncSetAttribute(gemm_proj_mma, cudaFuncAttributeMaxDynamicSharedMemorySize, DSMEM);

    zero_gram_kernel<<<576, 1024>>>();
    gemm_qkv_mma<<<dim3(K3C / 128, MROWS / 128), 256, DSMEM>>>(x, w_qkv);
    norm_kernel<<<2 * BHD, 128>>>();
    gram_kernel<<<dim3(16, BB * HH), 256>>>();
    softmax_kernel<<<BB * HH, 96>>>(temp);
    av_kernel<<<dim3(NN / 128, BB * HH), 256>>>();
    gemm_proj_mma<<<dim3(CC / 128, MROWS / 128), 256, DSMEM>>>(w_proj, b_proj, out);
}

// round 4
// speedup vs baseline: 4.1647x; 1.7218x over previous
#include <cuda_runtime.h>
#include <cuda_fp16.h>
#include <math.h>
#include <stdint.h>

// Problem constants
#define BB   8
#define NN   4096
#define CC   768
#define HH   8
#define HD   96
#define MROWS (BB*NN)      // 32768
#define K3C   (3*CC)       // 2304
#define BHD   (BB*HH*HD)   // 6144

// ---------------- scratch (device globals; no allocs allowed) ----------------
__device__ __align__(256) float g_q[BB*HH*HD*NN];        // [b][h][d][n]
__device__ __align__(256) float g_k[BB*HH*HD*NN];
__device__ __align__(256) float g_v[BB*HH*HD*NN];
__device__ __align__(256) float g_nq[BHD];
__device__ __align__(256) float g_nk[BHD];
__device__ __align__(256) float g_gram[BB*HH*HD*HD];
__device__ __align__(256) float g_ao[MROWS*CC];          // (B,N,C) row-major

// ======================= mma.sync helpers =======================
__device__ __forceinline__ uint32_t smem_u32(const void* p) {
    uint32_t a;
    asm("{ .reg .u64 t; cvta.to.shared.u64 t, %1; cvt.u32.u64 %0, t; }"
        : "=r"(a) : "l"(p));
    return a;
}
__device__ __forceinline__ void ldm_x4(uint32_t* r, uint32_t addr) {
    asm volatile("ldmatrix.sync.aligned.m8n8.x4.shared.b16 {%0,%1,%2,%3}, [%4];"
        : "=r"(r[0]), "=r"(r[1]), "=r"(r[2]), "=r"(r[3]) : "r"(addr));
}
__device__ __forceinline__ void mma_fp16(float* c, const uint32_t* a, const uint32_t* b) {
    asm volatile("mma.sync.aligned.m16n8k16.row.col.f32.f16.f16.f32 "
        "{%0,%1,%2,%3}, {%4,%5,%6,%7}, {%8,%9}, {%0,%1,%2,%3};"
        : "+f"(c[0]), "+f"(c[1]), "+f"(c[2]), "+f"(c[3])
        : "r"(a[0]), "r"(a[1]), "r"(a[2]), "r"(a[3]), "r"(b[0]), "r"(b[1]));
}

// smem tile geometry: 128 rows x 32 fp16, padded stride 40 halves (80B)
#define TROW 80                     // bytes per row
#define TSZ  (128*TROW)             // 10240 B per tile
#define STAGE (2*TSZ)               // A, B
#define DSMEM (2*STAGE)             // 40960 B
#define KC 32
#define NCH (CC/KC)                 // 24

// convert fp32 float4 -> fp16x4, store 8B
__device__ __forceinline__ void h_store(char* dst, float4 v) {
    __half2 h0 = __float22half2_rn(make_float2(v.x, v.y));
    __half2 h1 = __float22half2_rn(make_float2(v.z, v.w));
    uint2 u;
    u.x = *reinterpret_cast<uint32_t*>(&h0);
    u.y = *reinterpret_cast<uint32_t*>(&h1);
    *(uint2*)dst = u;
}

// mainloop: acc[i(m16)][j(n8)][reg], A rows->M, B rows->N, both K-major ld=CC
__device__ __forceinline__ void mma_mainloop(
    const float* __restrict__ A, const float* __restrict__ B,
    int m0, int n0, float acc[4][4][4], char* sm)
{
    const int tid = threadIdx.x;
    const int wid = tid >> 5, lane = tid & 31;
    const int wm = (wid >> 2) * 64;
    const int wn = (wid & 3) * 32;
    const uint32_t sbase = smem_u32(sm);

    const int lrow = tid >> 3;          // 0..31
    const int lc4 = (tid & 7) * 4;      // col (floats)

    const uint32_t a_l = (uint32_t)(wm + (lane & 15)) * TROW + ((lane >> 4) << 4);
    const uint32_t b_l = (uint32_t)(wn + (lane & 7) + ((lane >> 4) & 1) * 8) * TROW
                       + (((lane >> 3) & 1) << 4);

    float4 ra[4], rb[4];
#pragma unroll
    for (int it = 0; it < 4; it++) {
        ra[it] = *(const float4*)(A + (size_t)(m0 + lrow + it * 32) * CC + lc4);
        rb[it] = *(const float4*)(B + (size_t)(n0 + lrow + it * 32) * CC + lc4);
    }
#pragma unroll
    for (int it = 0; it < 4; it++) {
        int off = (lrow + it * 32) * TROW + lc4 * 2;
        h_store(sm + off, ra[it]);
        h_store(sm + TSZ + off, rb[it]);
    }
    __syncthreads();

    for (int c = 0; c < NCH; c++) {
        if (c < NCH - 1) {
            int k0 = (c + 1) * KC;
#pragma unroll
            for (int it = 0; it < 4; it++) {
                ra[it] = *(const float4*)(A + (size_t)(m0 + lrow + it * 32) * CC + k0 + lc4);
                rb[it] = *(const float4*)(B + (size_t)(n0 + lrow + it * 32) * CC + k0 + lc4);
            }
        }
        const uint32_t st = sbase + (uint32_t)(c & 1) * STAGE;
#pragma unroll
        for (int kk = 0; kk < 2; kk++) {
            uint32_t ah[4][4], bh[2][4];
#pragma unroll
            for (int i = 0; i < 4; i++)
                ldm_x4(ah[i], st + a_l + kk * 32 + i * 16 * TROW);
#pragma unroll
            for (int j = 0; j < 2; j++)
                ldm_x4(bh[j], st + TSZ + b_l + kk * 32 + j * 16 * TROW);
#pragma unroll
            for (int i = 0; i < 4; i++)
#pragma unroll
                for (int j4 = 0; j4 < 4; j4++)
                    mma_fp16(acc[i][j4], ah[i], &bh[j4 >> 1][(j4 & 1) * 2]);
        }
        if (c < NCH - 1) {
            char* ns = sm + ((c + 1) & 1) * STAGE;
#pragma unroll
            for (int it = 0; it < 4; it++) {
                int off = (lrow + it * 32) * TROW + lc4 * 2;
                h_store(ns + off, ra[it]);
                h_store(ns + TSZ + off, rb[it]);
            }
        }
        __syncthreads();
    }
}

// ---- QKV GEMM: M = qkv features (w rows), N = tokens; scatter to q/k/v [d][n]
__global__ __launch_bounds__(256, 2) void gemm_qkv_mma(
    const float* __restrict__ x, const float* __restrict__ w)
{
    extern __shared__ char sm[];
    const int m0 = blockIdx.x * 128;   // feature tile (of 2304)
    const int n0 = blockIdx.y * 128;   // token tile (of 32768)
    float acc[4][4][4];
#pragma unroll
    for (int i = 0; i < 4; i++)
#pragma unroll
        for (int j = 0; j < 4; j++)
#pragma unroll
            for (int r = 0; r < 4; r++) acc[i][j][r] = 0.0f;

    mma_mainloop(w, x, m0, n0, acc, sm);

    const int tid = threadIdx.x;
    const int wid = tid >> 5, lane = tid & 31;
    const int wm = (wid >> 2) * 64, wn = (wid & 3) * 32;
    const int b = n0 >> 12;
    const int ntk = (n0 & (NN - 1)) + wn + (lane & 3) * 2;
#pragma unroll
    for (int i = 0; i < 4; i++) {
#pragma unroll
        for (int half = 0; half < 2; half++) {
            int f = m0 + wm + i * 16 + (lane >> 2) + half * 8;
            int t = f / CC;
            int rem = f - t * CC;
            int h = rem / HD, d = rem - h * HD;
            float* dst = (t == 0) ? g_q : (t == 1) ? g_k : g_v;
            float* rowp = dst + ((size_t)(b * HH + h) * HD + d) * NN;
#pragma unroll
            for (int j4 = 0; j4 < 4; j4++) {
                *(float2*)&rowp[ntk + j4 * 8] =
                    make_float2(acc[i][j4][half * 2], acc[i][j4][half * 2 + 1]);
            }
        }
    }
}

// ---- Proj GEMM: M = tokens (g_ao rows), N = out features; out coalesced ----
__global__ __launch_bounds__(256, 2) void gemm_proj_mma(
    const float* __restrict__ w, const float* __restrict__ bias,
    float* __restrict__ out)
{
    extern __shared__ char sm[];
    const int n0 = blockIdx.x * 128;   // feature tile (of 768)
    const int m0 = blockIdx.y * 128;   // token tile
    float acc[4][4][4];
#pragma unroll
    for (int i = 0; i < 4; i++)
#pragma unroll
        for (int j = 0; j < 4; j++)
#pragma unroll
            for (int r = 0; r < 4; r++) acc[i][j][r] = 0.0f;

    mma_mainloop(g_ao, w, m0, n0, acc, sm);

    const int tid = threadIdx.x;
    const int wid = tid >> 5, lane = tid & 31;
    const int wm = (wid >> 2) * 64, wn = (wid & 3) * 32;
    float2 bv[4];
#pragma unroll
    for (int j4 = 0; j4 < 4; j4++)
        bv[j4] = *(const float2*)&bias[n0 + wn + j4 * 8 + (lane & 3) * 2];
#pragma unroll
    for (int i = 0; i < 4; i++) {
#pragma unroll
        for (int half = 0; half < 2; half++) {
            int tok = m0 + wm + i * 16 + (lane >> 2) + half * 8;
            float* rowp = out + (size_t)tok * CC + n0 + wn + (lane & 3) * 2;
#pragma unroll
            for (int j4 = 0; j4 < 4; j4++) {
                *(float2*)&rowp[j4 * 8] =
                    make_float2(acc[i][j4][half * 2] + bv[j4].x,
                                acc[i][j4][half * 2 + 1] + bv[j4].y);
            }
        }
    }
}

// ---------------- kernel 0: zero gram accumulator ----------------
__global__ void zero_gram_kernel() {
    int i = blockIdx.x * blockDim.x + threadIdx.x;
    if (i < BB*HH*HD*HD) g_gram[i] = 0.0f;
}

// ---------------- kernel 2: row L2 norms over N ----------------
__global__ void norm_kernel() {
    int row = blockIdx.x;
    bool isq = row < BHD;
    int r = isq ? row : row - BHD;
    const float* p = (isq ? g_q : g_k) + (size_t)r * NN;
    float s = 0.0f;
    for (int i = threadIdx.x; i < NN; i += 128) {
        float v = p[i];
        s += v * v;
    }
    __shared__ float red[4];
#pragma unroll
    for (int o = 16; o; o >>= 1) s += __shfl_xor_sync(0xffffffff, s, o);
    if ((threadIdx.x & 31) == 0) red[threadIdx.x >> 5] = s;
    __syncthreads();
    if (threadIdx.x == 0) {
        float t = red[0] + red[1] + red[2] + red[3];
        (isq ? g_nq : g_nk)[r] = fmaxf(sqrtf(t), 1e-12f);
    }
}

// ---------------- kernel 3: Gram = q @ k^T over N (split-N, atomic) --------
__global__ __launch_bounds__(256) void gram_kernel() {
    const int bh = blockIdx.y;
    const int n0 = blockIdx.x * 256;
    const float* qb = g_q + (size_t)bh * HD * NN;
    const float* kb = g_k + (size_t)bh * HD * NN;
    __shared__ float qs[16][100];
    __shared__ float ks[16][100];
    const int tid = threadIdx.x;
    const int tx = tid & 15, ty = tid >> 4;

    float acc[6][6];
#pragma unroll
    for (int i = 0; i < 6; i++)
#pragma unroll
        for (int j = 0; j < 6; j++) acc[i][j] = 0.0f;

    for (int nt = 0; nt < 256; nt += 16) {
#pragma unroll
        for (int r = 0; r < 6; r++) {
            int idx = r * 256 + tid;
            int nn = idx & 15;
            int d = idx >> 4;
            qs[nn][d] = qb[(size_t)d * NN + n0 + nt + nn];
            ks[nn][d] = kb[(size_t)d * NN + n0 + nt + nn];
        }
        __syncthreads();
#pragma unroll
        for (int nn = 0; nn < 16; nn++) {
            float a[6], c[6];
#pragma unroll
            for (int i = 0; i < 6; i++) a[i] = qs[nn][ty * 6 + i];
#pragma unroll
            for (int j = 0; j < 6; j++) c[j] = ks[nn][tx * 6 + j];
#pragma unroll
            for (int i = 0; i < 6; i++)
#pragma unroll
                for (int j = 0; j < 6; j++) acc[i][j] += a[i] * c[j];
        }
        __syncthreads();
    }
    float* G = g_gram + (size_t)bh * HD * HD;
#pragma unroll
    for (int i = 0; i < 6; i++)
#pragma unroll
        for (int j = 0; j < 6; j++)
            atomicAdd(&G[(ty * 6 + i) * HD + tx * 6 + j], acc[i][j]);
}

// ---------------- kernel 4: scale + softmax per (b,h) row ----------------
__global__ void softmax_kernel(const float* __restrict__ temp) {
    const int bh = blockIdx.x;
    const int h = bh & (HH - 1);
    const int d = threadIdx.x;
    __shared__ float snk[HD];
    if (d < HD) snk[d] = g_nk[bh * HD + d];
    __syncthreads();
    if (d >= HD) return;
    float* row = g_gram + (size_t)bh * HD * HD + d * HD;
    const float scale = temp[h] / g_nq[bh * HD + d];
    float vals[HD];
    float mx = -1e30f;
    for (int e = 0; e < HD; e++) {
        float v = row[e] * scale / snk[e];
        vals[e] = v;
        mx = fmaxf(mx, v);
    }
    float s = 0.0f;
    for (int e = 0; e < HD; e++) {
        float ex = expf(vals[e] - mx);
        vals[e] = ex;
        s += ex;
    }
    float inv = 1.0f / s;
    for (int e = 0; e < HD; e++) row[e] = vals[e] * inv;
}

// ---------------- kernel 5: out = A @ v, write (B,N,C) layout ----------------
__global__ __launch_bounds__(256) void av_kernel() {
    const int bh = blockIdx.y;
    const int n0 = blockIdx.x * 128;
    const int bb = bh >> 3, h = bh & 7;
    __shared__ float Asm[HD][97];
    __shared__ float vs[16][128];
    const int tid = threadIdx.x;
    const int tx = tid & 15, ty = tid >> 4;

    const float* G = g_gram + (size_t)bh * HD * HD;
#pragma unroll
    for (int r = 0; r < 36; r++) {
        int idx = r * 256 + tid;
        Asm[idx / HD][idx % HD] = G[idx];
    }
    const float* vb = g_v + (size_t)bh * HD * NN;

    float acc[6][8];
#pragma unroll
    for (int i = 0; i < 6; i++)
#pragma unroll
        for (int j = 0; j < 8; j++) acc[i][j] = 0.0f;

    for (int e0 = 0; e0 < HD; e0 += 16) {
#pragma unroll
        for (int r = 0; r < 8; r++) {
            int idx = r * 256 + tid;
            int nn = idx & 127;
            int ee = idx >> 7;
            vs[ee][nn] = vb[(size_t)(e0 + ee) * NN + n0 + nn];
        }
        __syncthreads();
#pragma unroll
        for (int ee = 0; ee < 16; ee++) {
            float a[6], vv[8];
#pragma unroll
            for (int i = 0; i < 6; i++) a[i] = Asm[ty * 6 + i][e0 + ee];
#pragma unroll
            for (int j = 0; j < 8; j++) vv[j] = vs[ee][tx + j * 16];
#pragma unroll
            for (int i = 0; i < 6; i++)
#pragma unroll
                for (int j = 0; j < 8; j++) acc[i][j] += a[i] * vv[j];
        }
        __syncthreads();
    }
#pragma unroll
    for (int i = 0; i < 6; i++) {
        int d = ty * 6 + i;
#pragma unroll
        for (int j = 0; j < 8; j++) {
            int n = n0 + tx + j * 16;
            g_ao[((size_t)(bb * NN + n)) * CC + h * HD + d] = acc[i][j];
        }
    }
}

// ---------------- launch ----------------
extern "C" void kernel_launch(void* const* d_in, const int* in_sizes, int n_in,
                              void* d_out, int out_size)
{
    const float* x      = (const float*)d_in[0];
    const float* w_qkv  = (const float*)d_in[1];
    const float* temp   = (const float*)d_in[2];
    const float* w_proj = (const float*)d_in[3];
    const float* b_proj = (const float*)d_in[4];
    float* out = (float*)d_out;

    cudaFuncSetAttribute(gemm_qkv_mma, cudaFuncAttributeMaxDynamicSharedMemorySize, DSMEM);
    cudaFuncSetAttribute(gemm_proj_mma, cudaFuncAttributeMaxDynamicSharedMemorySize, DSMEM);

    zero_gram_kernel<<<576, 1024>>>();
    gemm_qkv_mma<<<dim3(K3C / 128, MROWS / 128), 256, DSMEM>>>(x, w_qkv);
    norm_kernel<<<2 * BHD, 128>>>();
    gram_kernel<<<dim3(16, BB * HH), 256>>>();
    softmax_kernel<<<BB * HH, 96>>>(temp);
    av_kernel<<<dim3(NN / 128, BB * HH), 256>>>();
    gemm_proj_mma<<<dim3(CC / 128, MROWS / 128), 256, DSMEM>>>(w_proj, b_proj, out);
}

// round 5
// speedup vs baseline: 5.7498x; 1.3806x over previous
#include <cuda_runtime.h>
#include <cuda_fp16.h>
#include <math.h>
#include <stdint.h>

// Problem constants
#define BB   8
#define NN   4096
#define CC   768
#define HH   8
#define HD   96
#define MROWS (BB*NN)      // 32768
#define K3C   (3*CC)       // 2304
#define BHD   (BB*HH*HD)   // 6144

// ---------------- scratch (device globals; no allocs allowed) ----------------
__device__ __align__(256) __half g_qh[BB*HH*HD*NN];      // [b][h][d][n] fp16
__device__ __align__(256) __half g_kh[BB*HH*HD*NN];
__device__ __align__(256) __half g_vh[BB*HH*HD*NN];
__device__ __align__(256) float g_nq[BHD];
__device__ __align__(256) float g_nk[BHD];
__device__ __align__(256) float g_gram[BB*HH*HD*HD];     // fp32 accumulators
__device__ __align__(256) __half g_attn[BB*HH*HD*HD];    // softmaxed, fp16
__device__ __align__(256) float g_ao[MROWS*CC];          // (B,N,C) row-major

// ======================= mma.sync helpers =======================
__device__ __forceinline__ uint32_t smem_u32(const void* p) {
    uint32_t a;
    asm("{ .reg .u64 t; cvta.to.shared.u64 t, %1; cvt.u32.u64 %0, t; }"
        : "=r"(a) : "l"(p));
    return a;
}
__device__ __forceinline__ void ldm_x4(uint32_t* r, uint32_t addr) {
    asm volatile("ldmatrix.sync.aligned.m8n8.x4.shared.b16 {%0,%1,%2,%3}, [%4];"
        : "=r"(r[0]), "=r"(r[1]), "=r"(r[2]), "=r"(r[3]) : "r"(addr));
}
__device__ __forceinline__ void ldm_x2(uint32_t* r, uint32_t addr) {
    asm volatile("ldmatrix.sync.aligned.m8n8.x2.shared.b16 {%0,%1}, [%2];"
        : "=r"(r[0]), "=r"(r[1]) : "r"(addr));
}
__device__ __forceinline__ void ldm_x4_trans(uint32_t* r, uint32_t addr) {
    asm volatile("ldmatrix.sync.aligned.m8n8.x4.trans.shared.b16 {%0,%1,%2,%3}, [%4];"
        : "=r"(r[0]), "=r"(r[1]), "=r"(r[2]), "=r"(r[3]) : "r"(addr));
}
__device__ __forceinline__ void mma_fp16(float* c, const uint32_t* a, const uint32_t* b) {
    asm volatile("mma.sync.aligned.m16n8k16.row.col.f32.f16.f16.f32 "
        "{%0,%1,%2,%3}, {%4,%5,%6,%7}, {%8,%9}, {%0,%1,%2,%3};"
        : "+f"(c[0]), "+f"(c[1]), "+f"(c[2]), "+f"(c[3])
        : "r"(a[0]), "r"(a[1]), "r"(a[2]), "r"(a[3]), "r"(b[0]), "r"(b[1]));
}

// ======================= big GEMMs (unchanged mainloop) =======================
#define TROW 80
#define TSZ  (128*TROW)
#define STAGE (2*TSZ)
#define DSMEM (2*STAGE)
#define KC 32
#define NCH (CC/KC)

__device__ __forceinline__ void h_store(char* dst, float4 v) {
    __half2 h0 = __float22half2_rn(make_float2(v.x, v.y));
    __half2 h1 = __float22half2_rn(make_float2(v.z, v.w));
    uint2 u;
    u.x = *reinterpret_cast<uint32_t*>(&h0);
    u.y = *reinterpret_cast<uint32_t*>(&h1);
    *(uint2*)dst = u;
}

__device__ __forceinline__ void mma_mainloop(
    const float* __restrict__ A, const float* __restrict__ B,
    int m0, int n0, float acc[4][4][4], char* sm)
{
    const int tid = threadIdx.x;
    const int wid = tid >> 5, lane = tid & 31;
    const int wm = (wid >> 2) * 64;
    const int wn = (wid & 3) * 32;
    const uint32_t sbase = smem_u32(sm);
    const int lrow = tid >> 3;
    const int lc4 = (tid & 7) * 4;
    const uint32_t a_l = (uint32_t)(wm + (lane & 15)) * TROW + ((lane >> 4) << 4);
    const uint32_t b_l = (uint32_t)(wn + (lane & 7) + ((lane >> 4) & 1) * 8) * TROW
                       + (((lane >> 3) & 1) << 4);

    float4 ra[4], rb[4];
#pragma unroll
    for (int it = 0; it < 4; it++) {
        ra[it] = *(const float4*)(A + (size_t)(m0 + lrow + it * 32) * CC + lc4);
        rb[it] = *(const float4*)(B + (size_t)(n0 + lrow + it * 32) * CC + lc4);
    }
#pragma unroll
    for (int it = 0; it < 4; it++) {
        int off = (lrow + it * 32) * TROW + lc4 * 2;
        h_store(sm + off, ra[it]);
        h_store(sm + TSZ + off, rb[it]);
    }
    __syncthreads();

    for (int c = 0; c < NCH; c++) {
        if (c < NCH - 1) {
            int k0 = (c + 1) * KC;
#pragma unroll
            for (int it = 0; it < 4; it++) {
                ra[it] = *(const float4*)(A + (size_t)(m0 + lrow + it * 32) * CC + k0 + lc4);
                rb[it] = *(const float4*)(B + (size_t)(n0 + lrow + it * 32) * CC + k0 + lc4);
            }
        }
        const uint32_t st = sbase + (uint32_t)(c & 1) * STAGE;
#pragma unroll
        for (int kk = 0; kk < 2; kk++) {
            uint32_t ah[4][4], bh[2][4];
#pragma unroll
            for (int i = 0; i < 4; i++)
                ldm_x4(ah[i], st + a_l + kk * 32 + i * 16 * TROW);
#pragma unroll
            for (int j = 0; j < 2; j++)
                ldm_x4(bh[j], st + TSZ + b_l + kk * 32 + j * 16 * TROW);
#pragma unroll
            for (int i = 0; i < 4; i++)
#pragma unroll
                for (int j4 = 0; j4 < 4; j4++)
                    mma_fp16(acc[i][j4], ah[i], &bh[j4 >> 1][(j4 & 1) * 2]);
        }
        if (c < NCH - 1) {
            char* ns = sm + ((c + 1) & 1) * STAGE;
#pragma unroll
            for (int it = 0; it < 4; it++) {
                int off = (lrow + it * 32) * TROW + lc4 * 2;
                h_store(ns + off, ra[it]);
                h_store(ns + TSZ + off, rb[it]);
            }
        }
        __syncthreads();
    }
}

// ---- QKV GEMM: M = qkv features, N = tokens; scatter fp16 to q/k/v [d][n]
__global__ __launch_bounds__(256, 2) void gemm_qkv_mma(
    const float* __restrict__ x, const float* __restrict__ w)
{
    extern __shared__ char sm[];
    const int m0 = blockIdx.x * 128;
    const int n0 = blockIdx.y * 128;
    float acc[4][4][4];
#pragma unroll
    for (int i = 0; i < 4; i++)
#pragma unroll
        for (int j = 0; j < 4; j++)
#pragma unroll
            for (int r = 0; r < 4; r++) acc[i][j][r] = 0.0f;

    mma_mainloop(w, x, m0, n0, acc, sm);

    const int tid = threadIdx.x;
    const int wid = tid >> 5, lane = tid & 31;
    const int wm = (wid >> 2) * 64, wn = (wid & 3) * 32;
    const int b = n0 >> 12;
    const int ntk = (n0 & (NN - 1)) + wn + (lane & 3) * 2;
#pragma unroll
    for (int i = 0; i < 4; i++) {
#pragma unroll
        for (int half = 0; half < 2; half++) {
            int f = m0 + wm + i * 16 + (lane >> 2) + half * 8;
            int t = f / CC;
            int rem = f - t * CC;
            int h = rem / HD, d = rem - h * HD;
            __half* dst = (t == 0) ? g_qh : (t == 1) ? g_kh : g_vh;
            __half* rowp = dst + ((size_t)(b * HH + h) * HD + d) * NN;
#pragma unroll
            for (int j4 = 0; j4 < 4; j4++) {
                *(__half2*)&rowp[ntk + j4 * 8] =
                    __floats2half2_rn(acc[i][j4][half * 2], acc[i][j4][half * 2 + 1]);
            }
        }
    }
}

// ---- Proj GEMM: M = tokens, N = out features; out coalesced ----
__global__ __launch_bounds__(256, 2) void gemm_proj_mma(
    const float* __restrict__ w, const float* __restrict__ bias,
    float* __restrict__ out)
{
    extern __shared__ char sm[];
    const int n0 = blockIdx.x * 128;
    const int m0 = blockIdx.y * 128;
    float acc[4][4][4];
#pragma unroll
    for (int i = 0; i < 4; i++)
#pragma unroll
        for (int j = 0; j < 4; j++)
#pragma unroll
            for (int r = 0; r < 4; r++) acc[i][j][r] = 0.0f;

    mma_mainloop(g_ao, w, m0, n0, acc, sm);

    const int tid = threadIdx.x;
    const int wid = tid >> 5, lane = tid & 31;
    const int wm = (wid >> 2) * 64, wn = (wid & 3) * 32;
    float2 bv[4];
#pragma unroll
    for (int j4 = 0; j4 < 4; j4++)
        bv[j4] = *(const float2*)&bias[n0 + wn + j4 * 8 + (lane & 3) * 2];
#pragma unroll
    for (int i = 0; i < 4; i++) {
#pragma unroll
        for (int half = 0; half < 2; half++) {
            int tok = m0 + wm + i * 16 + (lane >> 2) + half * 8;
            float* rowp = out + (size_t)tok * CC + n0 + wn + (lane & 3) * 2;
#pragma unroll
            for (int j4 = 0; j4 < 4; j4++) {
                *(float2*)&rowp[j4 * 8] =
                    make_float2(acc[i][j4][half * 2] + bv[j4].x,
                                acc[i][j4][half * 2 + 1] + bv[j4].y);
            }
        }
    }
}

// ---------------- zero gram accumulator ----------------
__global__ void zero_gram_kernel() {
    int i = blockIdx.x * blockDim.x + threadIdx.x;
    if (i < BB*HH*HD*HD) g_gram[i] = 0.0f;
}

// ---------------- row L2 norms over N (fp16 input, fp32 accum) ----------------
__global__ void norm_kernel() {
    int row = blockIdx.x;
    bool isq = row < BHD;
    int r = isq ? row : row - BHD;
    const __half2* p = (const __half2*)((isq ? g_qh : g_kh) + (size_t)r * NN);
    float s = 0.0f;
    for (int i = threadIdx.x; i < NN / 2; i += 128) {
        float2 v = __half22float2(p[i]);
        s += v.x * v.x + v.y * v.y;
    }
    __shared__ float red[4];
#pragma unroll
    for (int o = 16; o; o >>= 1) s += __shfl_xor_sync(0xffffffff, s, o);
    if ((threadIdx.x & 31) == 0) red[threadIdx.x >> 5] = s;
    __syncthreads();
    if (threadIdx.x == 0) {
        float t = red[0] + red[1] + red[2] + red[3];
        (isq ? g_nq : g_nk)[r] = fmaxf(sqrtf(t), 1e-12f);
    }
}

// ---------------- Gram via mma: C[d][e] = sum_n q[d][n]*k[e][n] ----------------
// grid (4 ksplit, 64 heads), 256 thr. smem tiles 96 x 64 halves, pitch 72.
#define GP 72
__global__ __launch_bounds__(256) void gram_mma() {
    const int bh = blockIdx.y;
    const int kseg = blockIdx.x;
    const __half* qb = g_qh + (size_t)bh * HD * NN;
    const __half* kb = g_kh + (size_t)bh * HD * NN;
    __shared__ __half qs[96 * GP];
    __shared__ __half ks[96 * GP];
    const int tid = threadIdx.x;
    const int wid = tid >> 5, lane = tid & 31;
    const int wm = (wid >> 2) * 48;
    const int wn = (wid & 3) * 24;
    const uint32_t qsb = smem_u32(qs), ksb = smem_u32(ks);
    const uint32_t a_base = qsb + ((wm + (lane & 15)) * GP + (lane >> 4) * 8) * 2;
    const uint32_t b_base = ksb + ((wn + (lane & 7)) * GP + ((lane >> 3) & 1) * 8) * 2;

    float acc[3][3][4];
#pragma unroll
    for (int i = 0; i < 3; i++)
#pragma unroll
        for (int j = 0; j < 3; j++)
#pragma unroll
            for (int r = 0; r < 4; r++) acc[i][j][r] = 0.0f;

    for (int it = 0; it < 16; it++) {
        int k0 = kseg * 1024 + it * 64;
#pragma unroll
        for (int l = 0; l < 6; l++) {
            int idx = l * 256 + tid;       // 0..1535
            int row = idx >> 4;
            int s = idx & 15;
            if (s < 8)
                *(uint4*)&qs[row * GP + s * 8] =
                    *(const uint4*)&qb[(size_t)row * NN + k0 + s * 8];
            else
                *(uint4*)&ks[row * GP + (s - 8) * 8] =
                    *(const uint4*)&kb[(size_t)row * NN + k0 + (s - 8) * 8];
        }
        __syncthreads();
#pragma unroll
        for (int kk = 0; kk < 4; kk++) {
            uint32_t a[3][4], bfr[3][2];
#pragma unroll
            for (int i = 0; i < 3; i++)
                ldm_x4(a[i], a_base + i * 16 * GP * 2 + kk * 32);
#pragma unroll
            for (int j = 0; j < 3; j++)
                ldm_x2(bfr[j], b_base + j * 8 * GP * 2 + kk * 32);
#pragma unroll
            for (int i = 0; i < 3; i++)
#pragma unroll
                for (int j = 0; j < 3; j++)
                    mma_fp16(acc[i][j], a[i], bfr[j]);
        }
        __syncthreads();
    }
    float* G = g_gram + (size_t)bh * HD * HD;
#pragma unroll
    for (int i = 0; i < 3; i++) {
        int d = wm + i * 16 + (lane >> 2);
#pragma unroll
        for (int j = 0; j < 3; j++) {
            int e = wn + j * 8 + (lane & 3) * 2;
            atomicAdd(&G[d * HD + e],       acc[i][j][0]);
            atomicAdd(&G[d * HD + e + 1],   acc[i][j][1]);
            atomicAdd(&G[(d + 8) * HD + e],     acc[i][j][2]);
            atomicAdd(&G[(d + 8) * HD + e + 1], acc[i][j][3]);
        }
    }
}

// ---------------- scale + softmax, emit fp16 attn ----------------
__global__ void softmax_kernel(const float* __restrict__ temp) {
    const int bh = blockIdx.x;
    const int h = bh & (HH - 1);
    const int d = threadIdx.x;
    __shared__ float snk[HD];
    if (d < HD) snk[d] = g_nk[bh * HD + d];
    __syncthreads();
    if (d >= HD) return;
    const float* row = g_gram + (size_t)bh * HD * HD + d * HD;
    __half* orow = g_attn + (size_t)bh * HD * HD + d * HD;
    const float scale = temp[h] / g_nq[bh * HD + d];
    float vals[HD];
    float mx = -1e30f;
    for (int e = 0; e < HD; e++) {
        float v = row[e] * scale / snk[e];
        vals[e] = v;
        mx = fmaxf(mx, v);
    }
    float s = 0.0f;
    for (int e = 0; e < HD; e++) {
        float ex = expf(vals[e] - mx);
        vals[e] = ex;
        s += ex;
    }
    float inv = 1.0f / s;
    for (int e = 0; e < HD; e++) orow[e] = __float2half(vals[e] * inv);
}

// ---------------- AV via mma: out[d][n] = sum_e attn[d][e]*v[e][n] ----------
// grid (32 token tiles, 64 heads), 256 thr.
#define AP 104   // attn smem pitch (halves)
#define VP 136   // v smem pitch (halves)
__global__ __launch_bounds__(256) void av_mma() {
    const int bh = blockIdx.y;
    const int n0 = blockIdx.x * 128;
    const int b = bh >> 3, h = bh & 7;
    __shared__ __half as_t[96 * AP];   // 19968 B
    __shared__ __half vs_t[96 * VP];   // 26112 B
    const int tid = threadIdx.x;
    const int wid = tid >> 5, lane = tid & 31;
    const int wm = (wid >> 2) * 48;    // d strip
    const int wn = (wid & 3) * 32;     // token strip

    // load attn tile 96x96
    const __half* at = g_attn + (size_t)bh * HD * HD;
#pragma unroll
    for (int l = 0; l < 5; l++) {
        int idx = l * 256 + tid;       // need 1152
        if (idx < 1152) {
            int row = idx / 12, c = idx % 12;
            *(uint4*)&as_t[row * AP + c * 8] = *(const uint4*)&at[row * HD + c * 8];
        }
    }
    // load v tile 96x128
    const __half* vb = g_vh + (size_t)bh * HD * NN;
#pragma unroll
    for (int l = 0; l < 6; l++) {
        int idx = l * 256 + tid;       // 1536
        int row = idx >> 4, c = idx & 15;
        *(uint4*)&vs_t[row * VP + c * 8] = *(const uint4*)&vb[(size_t)row * NN + n0 + c * 8];
    }
    __syncthreads();

    const uint32_t asb = smem_u32(as_t), vsb = smem_u32(vs_t);
    const uint32_t a_base = asb + ((wm + (lane & 15)) * AP + (lane >> 4) * 8) * 2;
    // trans addressing: e = kk*16 + (lane&7) + ((lane>>3)&1)*8 ; n = wn + j*16 + ((lane>>4)&1)*8
    const uint32_t b_roff = ((lane & 7) + ((lane >> 3) & 1) * 8) * VP * 2;
    const uint32_t b_coff = (wn + ((lane >> 4) & 1) * 8) * 2;

    float acc[3][4][4];
#pragma unroll
    for (int i = 0; i < 3; i++)
#pragma unroll
        for (int j = 0; j < 4; j++)
#pragma unroll
            for (int r = 0; r < 4; r++) acc[i][j][r] = 0.0f;

#pragma unroll
    for (int kk = 0; kk < 6; kk++) {
        uint32_t a[3][4], bt[2][4];
#pragma unroll
        for (int i = 0; i < 3; i++)
            ldm_x4(a[i], a_base + i * 16 * AP * 2 + kk * 32);
#pragma unroll
        for (int j = 0; j < 2; j++)
            ldm_x4_trans(bt[j], vsb + (kk * 16) * VP * 2 + b_roff + b_coff + j * 32);
#pragma unroll
        for (int i = 0; i < 3; i++)
#pragma unroll
            for (int jn = 0; jn < 4; jn++)
                mma_fp16(acc[i][jn], a[i], &bt[jn >> 1][(jn & 1) * 2]);
    }

    // epilogue: g_ao[(b,n)][h*96+d], fp32
#pragma unroll
    for (int i = 0; i < 3; i++) {
#pragma unroll
        for (int half = 0; half < 2; half++) {
            int d = wm + i * 16 + (lane >> 2) + half * 8;
            int col = h * HD + d;
#pragma unroll
            for (int jn = 0; jn < 4; jn++) {
                int n = n0 + wn + jn * 8 + (lane & 3) * 2;
                g_ao[((size_t)(b * NN + n)) * CC + col]     = acc[i][jn][half * 2];
                g_ao[((size_t)(b * NN + n + 1)) * CC + col] = acc[i][jn][half * 2 + 1];
            }
        }
    }
}

// ---------------- launch ----------------
extern "C" void kernel_launch(void* const* d_in, const int* in_sizes, int n_in,
                              void* d_out, int out_size)
{
    const float* x      = (const float*)d_in[0];
    const float* w_qkv  = (const float*)d_in[1];
    const float* temp   = (const float*)d_in[2];
    const float* w_proj = (const float*)d_in[3];
    const float* b_proj = (const float*)d_in[4];
    float* out = (float*)d_out;

    cudaFuncSetAttribute(gemm_qkv_mma, cudaFuncAttributeMaxDynamicSharedMemorySize, DSMEM);
    cudaFuncSetAttribute(gemm_proj_mma, cudaFuncAttributeMaxDynamicSharedMemorySize, DSMEM);

    zero_gram_kernel<<<576, 1024>>>();
    gemm_qkv_mma<<<dim3(K3C / 128, MROWS / 128), 256, DSMEM>>>(x, w_qkv);
    norm_kernel<<<2 * BHD, 128>>>();
    gram_mma<<<dim3(4, BB * HH), 256>>>();
    softmax_kernel<<<BB * HH, 96>>>(temp);
    av_mma<<<dim3(NN / 128, BB * HH), 256>>>();
    gemm_proj_mma<<<dim3(CC / 128, MROWS / 128), 256, DSMEM>>>(w_proj, b_proj, out);
}

// round 6
// speedup vs baseline: 6.5787x; 1.1442x over previous
#include <cuda_runtime.h>
#include <cuda_fp16.h>
#include <math.h>
#include <stdint.h>

// Problem constants
#define BB   8
#define NN   4096
#define CC   768
#define HH   8
#define HD   96
#define MROWS (BB*NN)      // 32768
#define K3C   (3*CC)       // 2304
#define BHD   (BB*HH*HD)   // 6144

// ---------------- scratch (device globals; no allocs allowed) ----------------
__device__ __align__(256) __half g_xh[MROWS*CC];         // fp16 copy of x
__device__ __align__(256) __half g_wqkvh[K3C*CC];        // fp16 w_qkv
__device__ __align__(256) __half g_wprojh[CC*CC];        // fp16 w_proj
__device__ __align__(256) __half g_qh[BB*HH*HD*NN];      // [b][h][d][n]
__device__ __align__(256) __half g_kh[BB*HH*HD*NN];
__device__ __align__(256) __half g_vh[BB*HH*HD*NN];
__device__ __align__(256) float g_nq[BHD];
__device__ __align__(256) float g_nk[BHD];
__device__ __align__(256) float g_gram[BB*HH*HD*HD];     // fp32 accumulators
__device__ __align__(256) __half g_attn[BB*HH*HD*HD];    // softmaxed, fp16
__device__ __align__(256) __half g_aoh[MROWS*CC];        // attention out, fp16

// ======================= helpers =======================
__device__ __forceinline__ uint32_t smem_u32(const void* p) {
    uint32_t a;
    asm("{ .reg .u64 t; cvta.to.shared.u64 t, %1; cvt.u32.u64 %0, t; }"
        : "=r"(a) : "l"(p));
    return a;
}
__device__ __forceinline__ void ldm_x4(uint32_t* r, uint32_t addr) {
    asm volatile("ldmatrix.sync.aligned.m8n8.x4.shared.b16 {%0,%1,%2,%3}, [%4];"
        : "=r"(r[0]), "=r"(r[1]), "=r"(r[2]), "=r"(r[3]) : "r"(addr));
}
__device__ __forceinline__ void ldm_x2(uint32_t* r, uint32_t addr) {
    asm volatile("ldmatrix.sync.aligned.m8n8.x2.shared.b16 {%0,%1}, [%2];"
        : "=r"(r[0]), "=r"(r[1]) : "r"(addr));
}
__device__ __forceinline__ void ldm_x4_trans(uint32_t* r, uint32_t addr) {
    asm volatile("ldmatrix.sync.aligned.m8n8.x4.trans.shared.b16 {%0,%1,%2,%3}, [%4];"
        : "=r"(r[0]), "=r"(r[1]), "=r"(r[2]), "=r"(r[3]) : "r"(addr));
}
__device__ __forceinline__ void mma_fp16(float* c, const uint32_t* a, const uint32_t* b) {
    asm volatile("mma.sync.aligned.m16n8k16.row.col.f32.f16.f16.f32 "
        "{%0,%1,%2,%3}, {%4,%5,%6,%7}, {%8,%9}, {%0,%1,%2,%3};"
        : "+f"(c[0]), "+f"(c[1]), "+f"(c[2]), "+f"(c[3])
        : "r"(a[0]), "r"(a[1]), "r"(a[2]), "r"(a[3]), "r"(b[0]), "r"(b[1]));
}
__device__ __forceinline__ void cp16(uint32_t s, const void* g) {
    asm volatile("cp.async.cg.shared.global [%0], [%1], 16;" :: "r"(s), "l"(g));
}
#define CP_COMMIT() asm volatile("cp.async.commit_group;" ::: "memory")
#define CP_WAIT1()  asm volatile("cp.async.wait_group 1;" ::: "memory")
#define CP_WAIT0()  asm volatile("cp.async.wait_group 0;" ::: "memory")

// ======================= fp32 -> fp16 convert =======================
__global__ void f2h_kernel(const float* __restrict__ src, __half* __restrict__ dst, int n4) {
    int i = blockIdx.x * blockDim.x + threadIdx.x;
    if (i < n4) {
        float4 v = ((const float4*)src)[i];
        __half2 a = __float22half2_rn(make_float2(v.x, v.y));
        __half2 b = __float22half2_rn(make_float2(v.z, v.w));
        uint2 u;
        u.x = *reinterpret_cast<uint32_t*>(&a);
        u.y = *reinterpret_cast<uint32_t*>(&b);
        ((uint2*)dst)[i] = u;
    }
}

// ======================= fp16-native GEMM mainloop =======================
// 128x128 tile, KC=64 halves, pitch 72 halves, 2-stage cp.async pipeline.
#define PH 72
#define TSZH (128*PH*2)      // 18432 B
#define STAGEH (2*TSZH)      // 36864 B (A + B)
#define DSMEMH (2*STAGEH)    // 73728 B
#define KCH 64
#define NCHH (CC/KCH)        // 12

__device__ __forceinline__ void issue_chunk(
    const __half* __restrict__ A, const __half* __restrict__ B,
    int m0, int n0, int k0, uint32_t st, int tid)
{
#pragma unroll
    for (int p = 0; p < 4; p++) {
        int slot = tid + p * 256;          // 0..1023
        int row = slot >> 3, c = slot & 7;
        cp16(st + row * (PH * 2) + c * 16,
             A + (size_t)(m0 + row) * CC + k0 + c * 8);
        cp16(st + TSZH + row * (PH * 2) + c * 16,
             B + (size_t)(n0 + row) * CC + k0 + c * 8);
    }
}

__device__ __forceinline__ void mma_mainloop_h(
    const __half* __restrict__ A, const __half* __restrict__ B,
    int m0, int n0, float acc[4][4][4], char* sm)
{
    const int tid = threadIdx.x;
    const int wid = tid >> 5, lane = tid & 31;
    const int wm = (wid >> 2) * 64;
    const int wn = (wid & 3) * 32;
    const uint32_t sbase = smem_u32(sm);
    const uint32_t a_l = (uint32_t)(wm + (lane & 15)) * (PH * 2) + ((lane >> 4) << 4);
    const uint32_t b_l = (uint32_t)(wn + (lane & 7) + ((lane >> 4) & 1) * 8) * (PH * 2)
                       + (((lane >> 3) & 1) << 4);

    issue_chunk(A, B, m0, n0, 0, sbase, tid);
    CP_COMMIT();

    for (int c = 0; c < NCHH; c++) {
        if (c + 1 < NCHH) {
            issue_chunk(A, B, m0, n0, (c + 1) * KCH,
                        sbase + (uint32_t)((c + 1) & 1) * STAGEH, tid);
            CP_COMMIT();
            CP_WAIT1();
        } else {
            CP_WAIT0();
        }
        __syncthreads();
        const uint32_t st = sbase + (uint32_t)(c & 1) * STAGEH;
#pragma unroll
        for (int kk = 0; kk < 4; kk++) {
            uint32_t ah[4][4], bh[2][4];
#pragma unroll
            for (int i = 0; i < 4; i++)
                ldm_x4(ah[i], st + a_l + kk * 32 + i * 16 * (PH * 2));
#pragma unroll
            for (int j = 0; j < 2; j++)
                ldm_x4(bh[j], st + TSZH + b_l + kk * 32 + j * 16 * (PH * 2));
#pragma unroll
            for (int i = 0; i < 4; i++)
#pragma unroll
                for (int j4 = 0; j4 < 4; j4++)
                    mma_fp16(acc[i][j4], ah[i], &bh[j4 >> 1][(j4 & 1) * 2]);
        }
        __syncthreads();
    }
}

// ---- QKV GEMM: M = qkv features, N = tokens; scatter fp16 to q/k/v [d][n]
__global__ __launch_bounds__(256, 2) void gemm_qkv_mma(void) {
    extern __shared__ char sm[];
    const int m0 = blockIdx.x * 128;
    const int n0 = blockIdx.y * 128;
    float acc[4][4][4];
#pragma unroll
    for (int i = 0; i < 4; i++)
#pragma unroll
        for (int j = 0; j < 4; j++)
#pragma unroll
            for (int r = 0; r < 4; r++) acc[i][j][r] = 0.0f;

    mma_mainloop_h(g_wqkvh, g_xh, m0, n0, acc, sm);

    const int tid = threadIdx.x;
    const int wid = tid >> 5, lane = tid & 31;
    const int wm = (wid >> 2) * 64, wn = (wid & 3) * 32;
    const int b = n0 >> 12;
    const int ntk = (n0 & (NN - 1)) + wn + (lane & 3) * 2;
#pragma unroll
    for (int i = 0; i < 4; i++) {
#pragma unroll
        for (int half = 0; half < 2; half++) {
            int f = m0 + wm + i * 16 + (lane >> 2) + half * 8;
            int t = f / CC;
            int rem = f - t * CC;
            int h = rem / HD, d = rem - h * HD;
            __half* dst = (t == 0) ? g_qh : (t == 1) ? g_kh : g_vh;
            __half* rowp = dst + ((size_t)(b * HH + h) * HD + d) * NN;
#pragma unroll
            for (int j4 = 0; j4 < 4; j4++) {
                *(__half2*)&rowp[ntk + j4 * 8] =
                    __floats2half2_rn(acc[i][j4][half * 2], acc[i][j4][half * 2 + 1]);
            }
        }
    }
}

// ---- Proj GEMM: M = tokens (g_aoh), N = out features; out fp32 coalesced ----
__global__ __launch_bounds__(256, 2) void gemm_proj_mma(
    const float* __restrict__ bias, float* __restrict__ out)
{
    extern __shared__ char sm[];
    const int n0 = blockIdx.x * 128;
    const int m0 = blockIdx.y * 128;
    float acc[4][4][4];
#pragma unroll
    for (int i = 0; i < 4; i++)
#pragma unroll
        for (int j = 0; j < 4; j++)
#pragma unroll
            for (int r = 0; r < 4; r++) acc[i][j][r] = 0.0f;

    mma_mainloop_h(g_aoh, g_wprojh, m0, n0, acc, sm);

    const int tid = threadIdx.x;
    const int wid = tid >> 5, lane = tid & 31;
    const int wm = (wid >> 2) * 64, wn = (wid & 3) * 32;
    float2 bv[4];
#pragma unroll
    for (int j4 = 0; j4 < 4; j4++)
        bv[j4] = *(const float2*)&bias[n0 + wn + j4 * 8 + (lane & 3) * 2];
#pragma unroll
    for (int i = 0; i < 4; i++) {
#pragma unroll
        for (int half = 0; half < 2; half++) {
            int tok = m0 + wm + i * 16 + (lane >> 2) + half * 8;
            float* rowp = out + (size_t)tok * CC + n0 + wn + (lane & 3) * 2;
#pragma unroll
            for (int j4 = 0; j4 < 4; j4++) {
                *(float2*)&rowp[j4 * 8] =
                    make_float2(acc[i][j4][half * 2] + bv[j4].x,
                                acc[i][j4][half * 2 + 1] + bv[j4].y);
            }
        }
    }
}

// ---------------- zero gram accumulator ----------------
__global__ void zero_gram_kernel() {
    int i = blockIdx.x * blockDim.x + threadIdx.x;
    if (i < BB*HH*HD*HD) g_gram[i] = 0.0f;
}

// ---------------- row L2 norms over N ----------------
__global__ void norm_kernel() {
    int row = blockIdx.x;
    bool isq = row < BHD;
    int r = isq ? row : row - BHD;
    const __half2* p = (const __half2*)((isq ? g_qh : g_kh) + (size_t)r * NN);
    float s = 0.0f;
    for (int i = threadIdx.x; i < NN / 2; i += 128) {
        float2 v = __half22float2(p[i]);
        s += v.x * v.x + v.y * v.y;
    }
    __shared__ float red[4];
#pragma unroll
    for (int o = 16; o; o >>= 1) s += __shfl_xor_sync(0xffffffff, s, o);
    if ((threadIdx.x & 31) == 0) red[threadIdx.x >> 5] = s;
    __syncthreads();
    if (threadIdx.x == 0) {
        float t = red[0] + red[1] + red[2] + red[3];
        (isq ? g_nq : g_nk)[r] = fmaxf(sqrtf(t), 1e-12f);
    }
}

// ---------------- Gram via mma ----------------
#define GP 72
__global__ __launch_bounds__(256) void gram_mma() {
    const int bh = blockIdx.y;
    const int kseg = blockIdx.x;
    const __half* qb = g_qh + (size_t)bh * HD * NN;
    const __half* kb = g_kh + (size_t)bh * HD * NN;
    __shared__ __half qs[96 * GP];
    __shared__ __half ks[96 * GP];
    const int tid = threadIdx.x;
    const int wid = tid >> 5, lane = tid & 31;
    const int wm = (wid >> 2) * 48;
    const int wn = (wid & 3) * 24;
    const uint32_t qsb = smem_u32(qs), ksb = smem_u32(ks);
    const uint32_t a_base = qsb + ((wm + (lane & 15)) * GP + (lane >> 4) * 8) * 2;
    const uint32_t b_base = ksb + ((wn + (lane & 7)) * GP + ((lane >> 3) & 1) * 8) * 2;

    float acc[3][3][4];
#pragma unroll
    for (int i = 0; i < 3; i++)
#pragma unroll
        for (int j = 0; j < 3; j++)
#pragma unroll
            for (int r = 0; r < 4; r++) acc[i][j][r] = 0.0f;

    for (int it = 0; it < 16; it++) {
        int k0 = kseg * 1024 + it * 64;
#pragma unroll
        for (int l = 0; l < 6; l++) {
            int idx = l * 256 + tid;
            int row = idx >> 4;
            int s = idx & 15;
            if (s < 8)
                *(uint4*)&qs[row * GP + s * 8] =
                    *(const uint4*)&qb[(size_t)row * NN + k0 + s * 8];
            else
                *(uint4*)&ks[row * GP + (s - 8) * 8] =
                    *(const uint4*)&kb[(size_t)row * NN + k0 + (s - 8) * 8];
        }
        __syncthreads();
#pragma unroll
        for (int kk = 0; kk < 4; kk++) {
            uint32_t a[3][4], bfr[3][2];
#pragma unroll
            for (int i = 0; i < 3; i++)
                ldm_x4(a[i], a_base + i * 16 * GP * 2 + kk * 32);
#pragma unroll
            for (int j = 0; j < 3; j++)
                ldm_x2(bfr[j], b_base + j * 8 * GP * 2 + kk * 32);
#pragma unroll
            for (int i = 0; i < 3; i++)
#pragma unroll
                for (int j = 0; j < 3; j++)
                    mma_fp16(acc[i][j], a[i], bfr[j]);
        }
        __syncthreads();
    }
    float* G = g_gram + (size_t)bh * HD * HD;
#pragma unroll
    for (int i = 0; i < 3; i++) {
        int d = wm + i * 16 + (lane >> 2);
#pragma unroll
        for (int j = 0; j < 3; j++) {
            int e = wn + j * 8 + (lane & 3) * 2;
            atomicAdd(&G[d * HD + e],       acc[i][j][0]);
            atomicAdd(&G[d * HD + e + 1],   acc[i][j][1]);
            atomicAdd(&G[(d + 8) * HD + e],     acc[i][j][2]);
            atomicAdd(&G[(d + 8) * HD + e + 1], acc[i][j][3]);
        }
    }
}

// ---------------- scale + softmax, emit fp16 attn ----------------
__global__ void softmax_kernel(const float* __restrict__ temp) {
    const int bh = blockIdx.x;
    const int h = bh & (HH - 1);
    const int d = threadIdx.x;
    __shared__ float snk[HD];
    if (d < HD) snk[d] = g_nk[bh * HD + d];
    __syncthreads();
    if (d >= HD) return;
    const float* row = g_gram + (size_t)bh * HD * HD + d * HD;
    __half* orow = g_attn + (size_t)bh * HD * HD + d * HD;
    const float scale = temp[h] / g_nq[bh * HD + d];
    float vals[HD];
    float mx = -1e30f;
    for (int e = 0; e < HD; e++) {
        float v = row[e] * scale / snk[e];
        vals[e] = v;
        mx = fmaxf(mx, v);
    }
    float s = 0.0f;
    for (int e = 0; e < HD; e++) {
        float ex = expf(vals[e] - mx);
        vals[e] = ex;
        s += ex;
    }
    float inv = 1.0f / s;
    for (int e = 0; e < HD; e++) orow[e] = __float2half(vals[e] * inv);
}

// ---------------- AV via mma: out[d][n] = sum_e attn[d][e]*v[e][n] ----------
#define AP 104
#define VP 136
__global__ __launch_bounds__(256) void av_mma() {
    const int bh = blockIdx.y;
    const int n0 = blockIdx.x * 128;
    const int b = bh >> 3, h = bh & 7;
    __shared__ __half as_t[96 * AP];
    __shared__ __half vs_t[96 * VP];
    const int tid = threadIdx.x;
    const int wid = tid >> 5, lane = tid & 31;
    const int wm = (wid >> 2) * 48;
    const int wn = (wid & 3) * 32;

    const __half* at = g_attn + (size_t)bh * HD * HD;
#pragma unroll
    for (int l = 0; l < 5; l++) {
        int idx = l * 256 + tid;
        if (idx < 1152) {
            int row = idx / 12, c = idx % 12;
            *(uint4*)&as_t[row * AP + c * 8] = *(const uint4*)&at[row * HD + c * 8];
        }
    }
    const __half* vb = g_vh + (size_t)bh * HD * NN;
#pragma unroll
    for (int l = 0; l < 6; l++) {
        int idx = l * 256 + tid;
        int row = idx >> 4, c = idx & 15;
        *(uint4*)&vs_t[row * VP + c * 8] = *(const uint4*)&vb[(size_t)row * NN + n0 + c * 8];
    }
    __syncthreads();

    const uint32_t asb = smem_u32(as_t), vsb = smem_u32(vs_t);
    const uint32_t a_base = asb + ((wm + (lane & 15)) * AP + (lane >> 4) * 8) * 2;
    const uint32_t b_roff = ((lane & 7) + ((lane >> 3) & 1) * 8) * VP * 2;
    const uint32_t b_coff = (wn + ((lane >> 4) & 1) * 8) * 2;

    float acc[3][4][4];
#pragma unroll
    for (int i = 0; i < 3; i++)
#pragma unroll
        for (int j = 0; j < 4; j++)
#pragma unroll
            for (int r = 0; r < 4; r++) acc[i][j][r] = 0.0f;

#pragma unroll
    for (int kk = 0; kk < 6; kk++) {
        uint32_t a[3][4], bt[2][4];
#pragma unroll
        for (int i = 0; i < 3; i++)
            ldm_x4(a[i], a_base + i * 16 * AP * 2 + kk * 32);
#pragma unroll
        for (int j = 0; j < 2; j++)
            ldm_x4_trans(bt[j], vsb + (kk * 16) * VP * 2 + b_roff + b_coff + j * 32);
#pragma unroll
        for (int i = 0; i < 3; i++)
#pragma unroll
            for (int jn = 0; jn < 4; jn++)
                mma_fp16(acc[i][jn], a[i], &bt[jn >> 1][(jn & 1) * 2]);
    }

#pragma unroll
    for (int i = 0; i < 3; i++) {
#pragma unroll
        for (int half = 0; half < 2; half++) {
            int d = wm + i * 16 + (lane >> 2) + half * 8;
            int col = h * HD + d;
#pragma unroll
            for (int jn = 0; jn < 4; jn++) {
                int n = n0 + wn + jn * 8 + (lane & 3) * 2;
                g_aoh[((size_t)(b * NN + n)) * CC + col]     = __float2half(acc[i][jn][half * 2]);
                g_aoh[((size_t)(b * NN + n + 1)) * CC + col] = __float2half(acc[i][jn][half * 2 + 1]);
            }
        }
    }
}

// ---------------- launch ----------------
extern "C" void kernel_launch(void* const* d_in, const int* in_sizes, int n_in,
                              void* d_out, int out_size)
{
    const float* x      = (const float*)d_in[0];
    const float* w_qkv  = (const float*)d_in[1];
    const float* temp   = (const float*)d_in[2];
    const float* w_proj = (const float*)d_in[3];
    const float* b_proj = (const float*)d_in[4];
    float* out = (float*)d_out;

    cudaFuncSetAttribute(gemm_qkv_mma, cudaFuncAttributeMaxDynamicSharedMemorySize, DSMEMH);
    cudaFuncSetAttribute(gemm_proj_mma, cudaFuncAttributeMaxDynamicSharedMemorySize, DSMEMH);

    __half* xh_p;    cudaGetSymbolAddress((void**)&xh_p, g_xh);
    __half* wq_p;    cudaGetSymbolAddress((void**)&wq_p, g_wqkvh);
    __half* wp_p;    cudaGetSymbolAddress((void**)&wp_p, g_wprojh);

    f2h_kernel<<<(MROWS*CC/4 + 255)/256, 256>>>(x, xh_p, MROWS*CC/4);
    f2h_kernel<<<(K3C*CC/4 + 255)/256, 256>>>(w_qkv, wq_p, K3C*CC/4);
    f2h_kernel<<<(CC*CC/4 + 255)/256, 256>>>(w_proj, wp_p, CC*CC/4);
    zero_gram_kernel<<<576, 1024>>>();
    gemm_qkv_mma<<<dim3(K3C / 128, MROWS / 128), 256, DSMEMH>>>();
    norm_kernel<<<2 * BHD, 128>>>();
    gram_mma<<<dim3(4, BB * HH), 256>>>();
    softmax_kernel<<<BB * HH, 96>>>(temp);
    av_mma<<<dim3(NN / 128, BB * HH), 256>>>();
    gemm_proj_mma<<<dim3(CC / 128, MROWS / 128), 256, DSMEMH>>>(b_proj, out);
}